// round 4
// baseline (speedup 1.0000x reference)
#include <cuda_runtime.h>
#include <cstdint>

#define BATCH 16
#define HH    256
#define WW    256
#define CIN   32
#define COUT  32
#define TAPS  9

#define HA    144          // rows per image handled by IMMA path
#define HB    (HH - HA)    // rows per image handled by dp4a path (112)

#define RPC      4         // IMMA: output rows per CTA
#define PXC      128       // IMMA: pixels per CTA
#define NTHREADS 256

// IMMA x smem: 6 rows x 132 px x 32B, 16B-chunk swizzled
#define XPX   132
#define ROWB  (XPX * 32)

// ---- shared arena (union of both paths) ----
// A: sxA 25344 | sbf 9216 | biasA 128   = 34688
// B: sxB 33024 | swB 9216 | biasB 128   = 42368
#define AR_SBF   25344
#define AR_BIASA 34560
#define AR_SWB   33024
#define AR_BIASB 42240
#define AR_SIZE  42496

// B fragments in mma.m16n8k32 order: [tap][ntile][lane]
__device__ uint2    g_bfrag[TAPS][4][32];
// dp4a weights: [tap][co][j], j = ci-group of 4, int8 in {-4..4}
__device__ uint32_t g_wpk[TAPS][COUT][8];
__device__ float    g_bias[COUT];

// ---------------------------------------------------------------------------
// Prep: both weight layouts + summed bias. Deterministic every call.
// ---------------------------------------------------------------------------
__global__ void prep_kernel(const float* __restrict__ Wt, const float* __restrict__ bias)
{
    const int kt   = blockIdx.x;        // 9 blocks
    const int t    = threadIdx.x;       // 128 threads
    const int nt   = t >> 5;
    const int lane = t & 31;
    const int g    = lane >> 2;
    const int tg   = lane & 3;
    const int co   = nt * 8 + g;

    // IMMA B-fragment
    {
        uint32_t w0 = 0, w1 = 0;
        #pragma unroll
        for (int j = 0; j < 4; j++) {
            int ci0 = tg * 4 + j;
            int ci1 = 16 + tg * 4 + j;
            int s0 = 0, s1 = 0;
            #pragma unroll
            for (int m = 0; m < 4; m++) {
                float a = Wt[((((size_t)m * TAPS + kt) << 5) + ci0) * 32 + co];
                float b = Wt[((((size_t)m * TAPS + kt) << 5) + ci1) * 32 + co];
                s0 += (a >= 0.0f) ? 1 : -1;
                s1 += (b >= 0.0f) ? 1 : -1;
            }
            w0 |= ((uint32_t)(uint8_t)(int8_t)s0) << (8 * j);
            w1 |= ((uint32_t)(uint8_t)(int8_t)s1) << (8 * j);
        }
        g_bfrag[kt][nt][lane] = make_uint2(w0, w1);
    }

    // dp4a packed weights (2 entries per thread)
    for (int e = t; e < COUT * 8; e += 128) {
        int wco = e >> 3, j = e & 7;
        uint32_t word = 0;
        #pragma unroll
        for (int k = 0; k < 4; k++) {
            int ci = j * 4 + k;
            int s = 0;
            #pragma unroll
            for (int m = 0; m < 4; m++) {
                float w = Wt[((((size_t)m * TAPS + kt) << 5) + ci) * 32 + wco];
                s += (w >= 0.0f) ? 1 : -1;
            }
            word |= ((uint32_t)(uint8_t)(int8_t)s) << (8 * k);
        }
        g_wpk[kt][wco][j] = word;
    }

    if (kt == 0 && t < COUT) {
        float s = 0.0f;
        #pragma unroll
        for (int m = 0; m < 4; m++) s += bias[m * COUT + t];
        g_bias[t] = s;
    }
}

// sign-pack 4 floats -> 4 int8 bytes in {+1 (0x01), -1 (0xFF)}
__device__ __forceinline__ uint32_t pk4(float4 v)
{
    uint32_t b0 = ((uint32_t)(__float_as_int(v.x) >> 31) & 0xFEu) ^ 1u;
    uint32_t b1 = ((uint32_t)(__float_as_int(v.y) >> 31) & 0xFEu) ^ 1u;
    uint32_t b2 = ((uint32_t)(__float_as_int(v.z) >> 31) & 0xFEu) ^ 1u;
    uint32_t b3 = ((uint32_t)(__float_as_int(v.w) >> 31) & 0xFEu) ^ 1u;
    return b0 | (b1 << 8) | (b2 << 16) | (b3 << 24);
}

__device__ __forceinline__ uint32_t smem_u32(const void* p)
{
    uint32_t a;
    asm("{ .reg .u64 t; cvta.to.shared.u64 t, %1; cvt.u32.u64 %0, t; }" : "=r"(a) : "l"(p));
    return a;
}

// ---------------------------------------------------------------------------
// Fused kernel: CTA type by bid pattern (period 16: 9 IMMA + 7 dp4a)
// ---------------------------------------------------------------------------
__global__ void __launch_bounds__(NTHREADS, 2)
conv_kernel(const float* __restrict__ x, float* __restrict__ y)
{
    __shared__ __align__(16) char arena[AR_SIZE];

    const int tid  = threadIdx.x;
    const int bid  = blockIdx.x;
    const int grp  = bid >> 4;
    const int r16  = bid & 15;

    if (r16 < 9) {
        // =================== IMMA path: 4 rows x 128 px ===================
        const int id   = grp * 9 + r16;          // [0, 1152)
        const int img  = id / 72;
        const int rem  = id % 72;
        const int h0   = (rem >> 1) * RPC;       // [0, 144)
        const int p0   = (rem & 1) * PXC;
        const int lane = tid & 31;
        const int wid  = tid >> 5;

        uint2 (*sbf)[4][32] = (uint2 (*)[4][32])(arena + AR_SBF);
        float* sbias        = (float*)(arena + AR_BIASA);

        {
            const uint2* src = &g_bfrag[0][0][0];
            uint2*       dst = &sbf[0][0][0];
            for (int i = tid; i < TAPS * 4 * 32; i += NTHREADS) dst[i] = src[i];
        }
        if (tid < COUT) sbias[tid] = g_bias[tid];

        // binarize + pack x: 6 rows x 130 px, 16B-chunk swizzled
        for (int i = tid; i < 6 * 130 * 2; i += NTHREADS) {
            int row = i / 260;
            int j   = i - row * 260;
            int spx = j >> 1;
            int c   = j & 1;
            int hr  = h0 - 1 + row;
            int px  = p0 + spx - 1;
            uint4 v = make_uint4(0, 0, 0, 0);
            if ((unsigned)hr < (unsigned)HH && (unsigned)px < (unsigned)WW) {
                const float4* src = (const float4*)
                    (x + (((size_t)(img * HH + hr) * WW + px) << 5) + (c << 4));
                v.x = pk4(src[0]); v.y = pk4(src[1]);
                v.z = pk4(src[2]); v.w = pk4(src[3]);
            }
            uint32_t off = row * ROWB + spx * 32 +
                           (((uint32_t)c ^ ((uint32_t)(spx >> 2) & 1u)) << 4);
            *(uint4*)(arena + off) = v;
        }
        __syncthreads();

        const int r   = wid >> 1;
        const int wpx = (wid & 1) * 64;
        const int q      = lane >> 3;
        const int px_off = ((q & 1) << 3) + (lane & 7);
        const int chunk  = q >> 1;

        int acc[4][4][4];
        #pragma unroll
        for (int mt = 0; mt < 4; mt++)
            #pragma unroll
            for (int nt = 0; nt < 4; nt++)
                #pragma unroll
                for (int e = 0; e < 4; e++) acc[mt][nt][e] = 0;

        const uint32_t sx_base = smem_u32(arena);

        #pragma unroll 1
        for (int kt = 0; kt < TAPS; kt++) {
            const int kh = kt / 3;
            const int kw = kt - kh * 3;

            uint2 b[4];
            #pragma unroll
            for (int nt = 0; nt < 4; nt++) b[nt] = sbf[kt][nt][lane];

            const int xrow = (r + kh) * ROWB;
            #pragma unroll
            for (int mt = 0; mt < 4; mt++) {
                const int spx = wpx + mt * 16 + px_off + kw;
                const uint32_t addr = sx_base + xrow + spx * 32 +
                                      (((uint32_t)chunk ^ ((uint32_t)(spx >> 2) & 1u)) << 4);
                uint32_t a0, a1, a2, a3;
                asm volatile("ldmatrix.sync.aligned.m8n8.x4.shared.b16 {%0,%1,%2,%3}, [%4];"
                             : "=r"(a0), "=r"(a1), "=r"(a2), "=r"(a3) : "r"(addr));
                #pragma unroll
                for (int nt = 0; nt < 4; nt++) {
                    asm volatile(
                        "mma.sync.aligned.m16n8k32.row.col.s32.s8.s8.s32 "
                        "{%0,%1,%2,%3}, {%4,%5,%6,%7}, {%8,%9}, {%0,%1,%2,%3};"
                        : "+r"(acc[mt][nt][0]), "+r"(acc[mt][nt][1]),
                          "+r"(acc[mt][nt][2]), "+r"(acc[mt][nt][3])
                        : "r"(a0), "r"(a1), "r"(a2), "r"(a3),
                          "r"(b[nt].x), "r"(b[nt].y));
                }
            }
        }

        const int g2 = lane >> 2;
        const int tg = lane & 3;
        const int hrow = img * HH + h0 + r;
        #pragma unroll
        for (int mt = 0; mt < 4; mt++) {
            const int pxa = p0 + wpx + mt * 16 + g2;
            float* dsta = y + (((size_t)hrow * WW + pxa) << 5);
            float* dstb = dsta + (8 << 5);
            #pragma unroll
            for (int nt = 0; nt < 4; nt++) {
                const int co = nt * 8 + 2 * tg;
                const float bz0 = sbias[co], bz1 = sbias[co + 1];
                float2 oa, ob;
                oa.x = (float)acc[mt][nt][0] + bz0;
                oa.y = (float)acc[mt][nt][1] + bz1;
                ob.x = (float)acc[mt][nt][2] + bz0;
                ob.y = (float)acc[mt][nt][3] + bz1;
                *(float2*)(dsta + co) = oa;
                *(float2*)(dstb + co) = ob;
            }
        }
    } else {
        // =================== dp4a path: 2 rows x 256 px ===================
        const int id   = grp * 7 + (r16 - 9);    // [0, 896)
        const int img  = id / 56;
        const int pair = id % 56;
        const int h0   = HA + 2 * pair;          // first output row [144, 254]

        uint32_t (*sx)[WW + 2][8] = (uint32_t (*)[WW + 2][8])arena;  // 4 rows
        uint32_t (*sw)[COUT][8]   = (uint32_t (*)[COUT][8])(arena + AR_SWB);
        float* sbias              = (float*)(arena + AR_BIASB);

        // zero tile (covers col pads and row 257 edge)
        for (int i = tid; i < 4 * (WW + 2) * 8; i += NTHREADS)
            ((uint32_t*)sx)[i] = 0;
        __syncthreads();

        // binarize rows h0-1 .. h0+2
        for (int rr = 0; rr < 4; rr++) {
            int hr = h0 - 1 + rr;
            if ((unsigned)hr < (unsigned)HH) {
                const float4* src = (const float4*)(x + ((size_t)(img * HH + hr) * WW) * CIN);
                for (int i = tid; i < WW * 8; i += NTHREADS) {
                    int px = i >> 3, g = i & 7;
                    sx[rr][px + 1][g] = pk4(src[(size_t)px * 8 + g]);
                }
            }
        }
        for (int i = tid; i < TAPS * COUT * 8; i += NTHREADS)
            ((uint32_t*)sw)[i] = ((const uint32_t*)g_wpk)[i];
        if (tid < COUT) sbias[tid] = g_bias[tid];
        __syncthreads();

        const int s   = tid >> 7;      // which of the 2 output rows
        const int t   = tid & 127;
        const int px0 = t * 2;

        int acc0[COUT], acc1[COUT];
        #pragma unroll
        for (int co = 0; co < COUT; co++) { acc0[co] = 0; acc1[co] = 0; }

        #pragma unroll 1
        for (int tap = 0; tap < TAPS; tap++) {
            const int kh = tap / 3;
            const int kw = tap - kh * 3;
            const uint32_t* xp = &sx[s + kh][px0 + kw][0];
            const int4 xa0 = *(const int4*)(xp + 0);
            const int4 xa1 = *(const int4*)(xp + 4);
            const int4 xb0 = *(const int4*)(xp + 8);
            const int4 xb1 = *(const int4*)(xp + 12);

            const int4* wp = (const int4*)&sw[tap][0][0];
            #pragma unroll
            for (int co = 0; co < COUT; co++) {
                const int4 w0 = wp[co * 2 + 0];
                const int4 w1 = wp[co * 2 + 1];
                int s0 = acc0[co];
                s0 = __dp4a(xa0.x, w0.x, s0); s0 = __dp4a(xa0.y, w0.y, s0);
                s0 = __dp4a(xa0.z, w0.z, s0); s0 = __dp4a(xa0.w, w0.w, s0);
                s0 = __dp4a(xa1.x, w1.x, s0); s0 = __dp4a(xa1.y, w1.y, s0);
                s0 = __dp4a(xa1.z, w1.z, s0); s0 = __dp4a(xa1.w, w1.w, s0);
                int s1 = acc1[co];
                s1 = __dp4a(xb0.x, w0.x, s1); s1 = __dp4a(xb0.y, w0.y, s1);
                s1 = __dp4a(xb0.z, w0.z, s1); s1 = __dp4a(xb0.w, w0.w, s1);
                s1 = __dp4a(xb1.x, w1.x, s1); s1 = __dp4a(xb1.y, w1.y, s1);
                s1 = __dp4a(xb1.z, w1.z, s1); s1 = __dp4a(xb1.w, w1.w, s1);
                acc0[co] = s0; acc1[co] = s1;
            }
        }

        const int hrow = img * HH + h0 + s;
        float4* dst = (float4*)(y + (((size_t)hrow * WW + px0) << 5));
        #pragma unroll
        for (int q = 0; q < 8; q++) {
            float4 o;
            o.x = (float)acc0[q * 4 + 0] + sbias[q * 4 + 0];
            o.y = (float)acc0[q * 4 + 1] + sbias[q * 4 + 1];
            o.z = (float)acc0[q * 4 + 2] + sbias[q * 4 + 2];
            o.w = (float)acc0[q * 4 + 3] + sbias[q * 4 + 3];
            dst[q] = o;
        }
        #pragma unroll
        for (int q = 0; q < 8; q++) {
            float4 o;
            o.x = (float)acc1[q * 4 + 0] + sbias[q * 4 + 0];
            o.y = (float)acc1[q * 4 + 1] + sbias[q * 4 + 1];
            o.z = (float)acc1[q * 4 + 2] + sbias[q * 4 + 2];
            o.w = (float)acc1[q * 4 + 3] + sbias[q * 4 + 3];
            dst[8 + q] = o;
        }
    }
}

extern "C" void kernel_launch(void* const* d_in, const int* in_sizes, int n_in,
                              void* d_out, int out_size)
{
    const float* x = (const float*)d_in[0];   // [16,256,256,32]
    const float* W = (const float*)d_in[1];   // [4,3,3,32,32]
    const float* b = (const float*)d_in[2];   // [4,32]
    float* y = (float*)d_out;                 // [16,256,256,32]

    prep_kernel<<<TAPS, 128>>>(W, b);
    // 1152 IMMA CTAs + 896 dp4a CTAs, interleaved 9:7 per 16 bids
    conv_kernel<<<2048, NTHREADS>>>(x, y);
}

// round 5
// speedup vs baseline: 1.1565x; 1.1565x over previous
#include <cuda_runtime.h>
#include <cstdint>

#define BATCH 16
#define HH    256
#define WW    256
#define CIN   32
#define COUT  32
#define TAPS  9

#define RPC      8      // output rows per CTA
#define PXC      64     // pixels per CTA
#define NTHREADS 256

// x smem: 10 rows (RPC + 2 halo) x 66 px x 32B, 16B-chunk swizzled
#define XPX   66
#define ROWB  (XPX * 32)

// B fragments in exact mma order: [tap][ntile][lane] uint2
__device__ uint2 g_bfrag[TAPS][4][32];
__device__ float g_bias[COUT];

// ---------------------------------------------------------------------------
// Prep: w_sum = sum_m sign(W_m) (int8, in {-4..4}) packed straight into
// mma.m16n8k32 B-fragment order. Also summed bias. Deterministic every call.
// ---------------------------------------------------------------------------
__global__ void prep_kernel(const float* __restrict__ Wt, const float* __restrict__ bias)
{
    const int kt   = blockIdx.x;        // 9 blocks
    const int t    = threadIdx.x;       // 128 threads: nt*32 + lane
    const int nt   = t >> 5;
    const int lane = t & 31;
    const int g    = lane >> 2;         // n within 8
    const int tg   = lane & 3;          // k-byte group
    const int co   = nt * 8 + g;

    uint32_t w0 = 0, w1 = 0;
    #pragma unroll
    for (int j = 0; j < 4; j++) {
        int ci0 = tg * 4 + j;
        int ci1 = 16 + tg * 4 + j;
        int s0 = 0, s1 = 0;
        #pragma unroll
        for (int m = 0; m < 4; m++) {
            float a = Wt[((((size_t)m * TAPS + kt) << 5) + ci0) * 32 + co];
            float b = Wt[((((size_t)m * TAPS + kt) << 5) + ci1) * 32 + co];
            s0 += (a >= 0.0f) ? 1 : -1;
            s1 += (b >= 0.0f) ? 1 : -1;
        }
        w0 |= ((uint32_t)(uint8_t)(int8_t)s0) << (8 * j);
        w1 |= ((uint32_t)(uint8_t)(int8_t)s1) << (8 * j);
    }
    g_bfrag[kt][nt][lane] = make_uint2(w0, w1);

    if (kt == 0 && t < COUT) {
        float s = 0.0f;
        #pragma unroll
        for (int m = 0; m < 4; m++) s += bias[m * COUT + t];
        g_bias[t] = s;
    }
}

// sign-pack 4 floats -> 4 int8 bytes {+1 (0x01), -1 (0xFF)} via PRMT
// sign-replicate mode (selector nibble bit3): 3 PRMT + 1 LOP3.
__device__ __forceinline__ uint32_t pk4u(uint4 u)
{
    uint32_t s01, s23, m, out;
    asm("prmt.b32 %0, %1, %2, 0x00FB;" : "=r"(s01) : "r"(u.x), "r"(u.y));
    asm("prmt.b32 %0, %1, %2, 0x00FB;" : "=r"(s23) : "r"(u.z), "r"(u.w));
    asm("prmt.b32 %0, %1, %2, 0x5410;" : "=r"(m)   : "r"(s01), "r"(s23));
    out = (m & 0xFEFEFEFEu) ^ 0x01010101u;
    return out;
}

__device__ __forceinline__ uint32_t smem_u32(const void* p)
{
    uint32_t a;
    asm("{ .reg .u64 t; cvta.to.shared.u64 t, %1; cvt.u32.u64 %0, t; }" : "=r"(a) : "l"(p));
    return a;
}

// ---------------------------------------------------------------------------
// Conv kernel: implicit GEMM on IMMA (mma.sync m16n8k32 s8)
// CTA = 8 rows x 64 px. warp w = row w, 64 px x 32 co.
// ---------------------------------------------------------------------------
__global__ void __launch_bounds__(NTHREADS, 2)
conv_kernel(const float* __restrict__ x, float* __restrict__ y)
{
    __shared__ uint32_t sx[10 * ROWB / 4];         // 10 rows x 66 px x 32B
    __shared__ uint2    sbf[TAPS][4][32];
    __shared__ float    sbias[COUT];

    const int tid  = threadIdx.x;
    const int lane = tid & 31;
    const int wid  = tid >> 5;
    const int bid  = blockIdx.x;
    const int img  = bid >> 7;
    const int rem  = bid & 127;
    const int h0   = (rem >> 2) * RPC;             // 32 row-tiles
    const int p0   = (rem & 3) * PXC;              // 4 px-tiles

    // ---- stage B fragments + bias ----
    {
        const uint2* src = &g_bfrag[0][0][0];
        uint2*       dst = &sbf[0][0][0];
        for (int i = tid; i < TAPS * 4 * 32; i += NTHREADS) dst[i] = src[i];
    }
    if (tid < COUT) sbias[tid] = g_bias[tid];

    // ---- binarize + pack x: 10 rows x 66 px x 2 chunks = 1320 units ----
    // smem addr: row*ROWB + spx*32 + ((c ^ ((spx>>2)&1))<<4)
    #pragma unroll
    for (int k = 0; k < 6; k++) {
        int i = tid + k * NTHREADS;
        if (i < 10 * XPX * 2) {
            int row = i / (XPX * 2);
            int j   = i - row * (XPX * 2);
            int spx = j >> 1;
            int c   = j & 1;
            int hr  = h0 - 1 + row;
            int px  = p0 + spx - 1;
            uint32_t v0 = 0x01010101u, v1 = v0, v2 = v0, v3 = v0;
            bool inb = ((unsigned)hr < (unsigned)HH) & ((unsigned)px < (unsigned)WW);
            if (inb) {
                const uint4* src = (const uint4*)
                    (x + (((size_t)(img * HH + hr) * WW + px) << 5) + (c << 4));
                uint4 a = src[0], b = src[1], cc = src[2], d = src[3];
                v0 = pk4u(a); v1 = pk4u(b); v2 = pk4u(cc); v3 = pk4u(d);
            } else {
                v0 = v1 = v2 = v3 = 0u;     // SAME zero padding
            }
            uint32_t off = row * ROWB + spx * 32 +
                           (((uint32_t)c ^ ((uint32_t)(spx >> 2) & 1u)) << 4);
            *(uint4*)((char*)sx + off) = make_uint4(v0, v1, v2, v3);
        }
    }
    __syncthreads();

    // ---- warp tile: row = wid, 64 px x 32 co ----
    const int r = wid;

    // ldmatrix lane mapping
    const int q      = lane >> 3;
    const int px_off = ((q & 1) << 3) + (lane & 7);
    const int chunk  = q >> 1;

    int acc[4][4][4];
    #pragma unroll
    for (int mt = 0; mt < 4; mt++)
        #pragma unroll
        for (int nt = 0; nt < 4; nt++)
            #pragma unroll
            for (int e = 0; e < 4; e++) acc[mt][nt][e] = 0;

    const uint32_t sx_base = smem_u32(sx);

    #pragma unroll 1
    for (int kt = 0; kt < TAPS; kt++) {
        const int kh = kt / 3;
        const int kw = kt - kh * 3;

        uint2 b[4];
        #pragma unroll
        for (int nt = 0; nt < 4; nt++) b[nt] = sbf[kt][nt][lane];

        const int xrow = (r + kh) * ROWB;
        #pragma unroll
        for (int mt = 0; mt < 4; mt++) {
            const int spx = mt * 16 + px_off + kw;
            const uint32_t addr = sx_base + xrow + spx * 32 +
                                  (((uint32_t)chunk ^ ((uint32_t)(spx >> 2) & 1u)) << 4);
            uint32_t a0, a1, a2, a3;
            asm volatile("ldmatrix.sync.aligned.m8n8.x4.shared.b16 {%0,%1,%2,%3}, [%4];"
                         : "=r"(a0), "=r"(a1), "=r"(a2), "=r"(a3) : "r"(addr));
            #pragma unroll
            for (int nt = 0; nt < 4; nt++) {
                asm volatile(
                    "mma.sync.aligned.m16n8k32.row.col.s32.s8.s8.s32 "
                    "{%0,%1,%2,%3}, {%4,%5,%6,%7}, {%8,%9}, {%0,%1,%2,%3};"
                    : "+r"(acc[mt][nt][0]), "+r"(acc[mt][nt][1]),
                      "+r"(acc[mt][nt][2]), "+r"(acc[mt][nt][3])
                    : "r"(a0), "r"(a1), "r"(a2), "r"(a3),
                      "r"(b[nt].x), "r"(b[nt].y));
            }
        }
    }

    // ---- epilogue ----
    const int g2 = lane >> 2;
    const int tg = lane & 3;
    const int hrow = img * HH + h0 + r;
    #pragma unroll
    for (int mt = 0; mt < 4; mt++) {
        const int pxa = p0 + mt * 16 + g2;
        float* dsta = y + (((size_t)hrow * WW + pxa) << 5);
        float* dstb = dsta + (8 << 5);
        #pragma unroll
        for (int nt = 0; nt < 4; nt++) {
            const int co = nt * 8 + 2 * tg;
            const float bz0 = sbias[co], bz1 = sbias[co + 1];
            float2 oa, ob;
            oa.x = (float)acc[mt][nt][0] + bz0;
            oa.y = (float)acc[mt][nt][1] + bz1;
            ob.x = (float)acc[mt][nt][2] + bz0;
            ob.y = (float)acc[mt][nt][3] + bz1;
            *(float2*)(dsta + co) = oa;
            *(float2*)(dstb + co) = ob;
        }
    }
}

extern "C" void kernel_launch(void* const* d_in, const int* in_sizes, int n_in,
                              void* d_out, int out_size)
{
    const float* x = (const float*)d_in[0];   // [16,256,256,32]
    const float* W = (const float*)d_in[1];   // [4,3,3,32,32]
    const float* b = (const float*)d_in[2];   // [4,32]
    float* y = (float*)d_out;                 // [16,256,256,32]

    prep_kernel<<<TAPS, 128>>>(W, b);
    conv_kernel<<<BATCH * (HH / RPC) * (WW / PXC), NTHREADS>>>(x, y);
}